// round 13
// baseline (speedup 1.0000x reference)
#include <cuda_runtime.h>
#include <cuda_fp16.h>
#include <cstdint>
#include <math.h>

#define BATCH 8192
#define DHALF 1024
#define HID   4096
#define XCOLS 2048
#define WSLOT ((size_t)DHALF * HID)

// ---------------- scratch (device globals: allocation-free rule) -----------
__device__ __half g_act[(size_t)BATCH * DHALF];
__device__ __half g_hid[(size_t)BATCH * 2 * HID];   // s cols [0,4096), t cols [4096,8192)
__device__ __half g_wt[8 * WSLOT];
__device__ float g_s0[(size_t)BATCH * DHALF];
__device__ float g_s1[(size_t)BATCH * DHALF];
__device__ float g_t0[(size_t)BATCH * DHALF];
__device__ float g_t1[(size_t)BATCH * DHALF];

// ---------------- helpers ----------------------------------------------
__device__ __forceinline__ uint32_t smem_u32(const void* p) {
    uint32_t a;
    asm("{ .reg .u64 t; cvta.to.shared.u64 t, %1; cvt.u32.u64 %0, t; }" : "=r"(a) : "l"(p));
    return a;
}
__device__ __forceinline__ void cp16(uint32_t s, const void* g) {
    asm volatile("cp.async.cg.shared.global [%0], [%1], 16;" :: "r"(s), "l"(g));
}
__device__ __forceinline__ uint32_t pack_h2(__half a, __half b) {
    __half2 t = __halves2half2(a, b);
    return *reinterpret_cast<uint32_t*>(&t);
}
__device__ __forceinline__ void mma16816(float* d, const uint32_t* a, uint32_t b0, uint32_t b1) {
    asm volatile(
        "mma.sync.aligned.m16n8k16.row.col.f32.f16.f16.f32 "
        "{%0,%1,%2,%3}, {%4,%5,%6,%7}, {%8,%9}, {%0,%1,%2,%3};"
        : "+f"(d[0]), "+f"(d[1]), "+f"(d[2]), "+f"(d[3])
        : "r"(a[0]), "r"(a[1]), "r"(a[2]), "r"(a[3]), "r"(b0), "r"(b1));
}
__device__ __forceinline__ void ldsm4(uint32_t* r, uint32_t addr) {
    asm volatile("ldmatrix.sync.aligned.m8n8.x4.shared.b16 {%0,%1,%2,%3}, [%4];"
        : "=r"(r[0]), "=r"(r[1]), "=r"(r[2]), "=r"(r[3]) : "r"(addr));
}

#define PITCH 144u
#define TILEB_128 (128u * PITCH)             // 18432
#define STAGEB_2T (2u * TILEB_128)           // 36864 (A128 + B128)
#define SMEM_BYTES (3u * STAGEB_2T)          // 110592

// ---------------------------------------------------------------------------
// Layer-1 GEMM (merged s&t): hid[m, 0..8191] = relu(act @ [Ws|Wt]^T + [bs|bt])
// BM=128, BN=128, BK=64, 3 stages, 2 CTAs/SM, 8 warps (2m x 4n), warp 64x32.
// ---------------------------------------------------------------------------
#define L1_K 1024
#define L1_N 8192

__global__ __launch_bounds__(256, 2)
void gemm_l1(const __half* __restrict__ A,
             const __half* __restrict__ B,
             const float* __restrict__ bias0,
             const float* __restrict__ bias1,
             __half* __restrict__ Ch)
{
    extern __shared__ char smem[];
    const uint32_t sb = smem_u32(smem);
    const int tid = threadIdx.x;
    const int wid = tid >> 5;
    const int lid = tid & 31;
    const int wm = wid & 1;
    const int wn = wid >> 1;
    const int mBase = blockIdx.y * 128;
    const int nBase = blockIdx.x * 128;
    const float* __restrict__ bb = (nBase < HID) ? bias0 : bias1;

    auto load_stage = [&](int stage, int k0) {
        const uint32_t st = sb + stage * STAGEB_2T;
        #pragma unroll
        for (int j = 0; j < 4; ++j) {
            int i = tid + 256 * j;
            int r = i >> 3, c = i & 7;
            uint32_t off = (uint32_t)r * PITCH + (uint32_t)c * 16u;
            cp16(st + off,              A + (size_t)(mBase + r) * L1_K + k0 + c * 8);
            cp16(st + TILEB_128 + off,  B + (size_t)(nBase + r) * L1_K + k0 + c * 8);
        }
        asm volatile("cp.async.commit_group;" ::: "memory");
    };

    float acc[4][4][4];
    #pragma unroll
    for (int i = 0; i < 4; ++i)
        #pragma unroll
        for (int j = 0; j < 4; ++j)
            #pragma unroll
            for (int q = 0; q < 4; ++q) acc[i][j][q] = 0.f;

    const int NC = L1_K / 64;
    load_stage(0, 0);
    load_stage(1, 64);

    const int lr16 = lid & 15;
    const uint32_t lcol = (uint32_t)(lid >> 4) * 16u;

    for (int c = 0; c < NC; ++c) {
        const int s = c % 3;
        asm volatile("cp.async.wait_group 1;" ::: "memory");
        __syncthreads();
        if (c + 2 < NC) load_stage((c + 2) % 3, (c + 2) * 64);

        const uint32_t st = sb + s * STAGEB_2T;
        const uint32_t aAddr = st + (uint32_t)(wm * 64 + lr16) * PITCH + lcol;
        const uint32_t bAddr = st + TILEB_128 + (uint32_t)(wn * 32 + lr16) * PITCH + lcol;

        #pragma unroll
        for (int kb = 0; kb < 4; ++kb) {
            const uint32_t cOff = (uint32_t)kb * 32u;
            uint32_t ah[4][4], bh[2][4];
            #pragma unroll
            for (int mi = 0; mi < 4; ++mi)
                ldsm4(ah[mi], aAddr + (uint32_t)mi * (16u * PITCH) + cOff);
            #pragma unroll
            for (int g = 0; g < 2; ++g)
                ldsm4(bh[g], bAddr + (uint32_t)g * (16u * PITCH) + cOff);
            #pragma unroll
            for (int mi = 0; mi < 4; ++mi)
                #pragma unroll
                for (int ni = 0; ni < 4; ++ni)
                    mma16816(acc[mi][ni], ah[mi], bh[ni >> 1][ni & 1], bh[ni >> 1][(ni & 1) + 2]);
        }
    }

    const int lr = lid >> 2;
    const int q2 = (lid & 3) * 2;
    #pragma unroll
    for (int mi = 0; mi < 4; ++mi) {
        #pragma unroll
        for (int half = 0; half < 2; ++half) {
            const int m = mBase + wm * 64 + mi * 16 + lr + half * 8;
            #pragma unroll
            for (int ni = 0; ni < 4; ++ni) {
                const int n = nBase + wn * 32 + ni * 8 + q2;
                const int nb = n & (HID - 1);
                float v0 = fmaxf(acc[mi][ni][half * 2 + 0] + bb[nb],     0.f);
                float v1 = fmaxf(acc[mi][ni][half * 2 + 1] + bb[nb + 1], 0.f);
                *reinterpret_cast<uint32_t*>(&Ch[(size_t)m * L1_N + n]) =
                    pack_h2(__float2half(v0), __float2half(v1));
            }
        }
    }
}

// ---------------------------------------------------------------------------
// Layer-2 GEMM, K-split + z-batched:
// blockIdx.z: bit0 = chain (0=s, 1=t), bit1 = K-half.
// C_partial[m, n] = hid[m, z*4096 + kh*2048 + k] @ Wz[n, kh*2048 + k]  (K=2048)
// NO bias (added in ew_couple). BM=128, BN=128, BK=64, 3 stages, 2 CTAs/SM.
// ---------------------------------------------------------------------------
#define L2_KSPLIT 2048

__global__ __launch_bounds__(256, 2)
void gemm_l2(const __half* __restrict__ Ab,   // g_hid base, ld = 8192
             const __half* __restrict__ Wb,   // wt slot base z=0; z=1 at +WSLOT; ld = 4096
             float* __restrict__ S0, float* __restrict__ S1,
             float* __restrict__ T0, float* __restrict__ T1)
{
    extern __shared__ char smem[];
    const uint32_t sb = smem_u32(smem);
    const int tid = threadIdx.x;
    const int wid = tid >> 5;
    const int lid = tid & 31;
    const int wm = wid & 1;
    const int wn = wid >> 1;
    const int z  = blockIdx.z & 1;
    const int kh = blockIdx.z >> 1;
    const int mBase = blockIdx.y * 128;
    const int nBase = blockIdx.x * 128;

    const __half* __restrict__ A = Ab + (size_t)z * HID + (size_t)kh * L2_KSPLIT;
    const __half* __restrict__ B = Wb + (size_t)z * WSLOT + (size_t)kh * L2_KSPLIT;
    float* __restrict__ C = z ? (kh ? T1 : T0) : (kh ? S1 : S0);

    auto load_stage = [&](int stage, int k0) {
        const uint32_t st = sb + stage * STAGEB_2T;
        #pragma unroll
        for (int j = 0; j < 4; ++j) {
            int i = tid + 256 * j;
            int r = i >> 3, c = i & 7;
            uint32_t off = (uint32_t)r * PITCH + (uint32_t)c * 16u;
            cp16(st + off,             A + (size_t)(mBase + r) * (2 * HID) + k0 + c * 8);
            cp16(st + TILEB_128 + off, B + (size_t)(nBase + r) * HID + k0 + c * 8);
        }
        asm volatile("cp.async.commit_group;" ::: "memory");
    };

    float acc[4][4][4];
    #pragma unroll
    for (int i = 0; i < 4; ++i)
        #pragma unroll
        for (int j = 0; j < 4; ++j)
            #pragma unroll
            for (int q = 0; q < 4; ++q) acc[i][j][q] = 0.f;

    const int NC = L2_KSPLIT / 64;
    load_stage(0, 0);
    load_stage(1, 64);

    const int lr16 = lid & 15;
    const uint32_t lcol = (uint32_t)(lid >> 4) * 16u;

    for (int c = 0; c < NC; ++c) {
        const int s = c % 3;
        asm volatile("cp.async.wait_group 1;" ::: "memory");
        __syncthreads();
        if (c + 2 < NC) load_stage((c + 2) % 3, (c + 2) * 64);

        const uint32_t st = sb + s * STAGEB_2T;
        const uint32_t aAddr = st + (uint32_t)(wm * 64 + lr16) * PITCH + lcol;
        const uint32_t bAddr = st + TILEB_128 + (uint32_t)(wn * 32 + lr16) * PITCH + lcol;

        #pragma unroll
        for (int kb = 0; kb < 4; ++kb) {
            const uint32_t cOff = (uint32_t)kb * 32u;
            uint32_t ah[4][4], bh[2][4];
            #pragma unroll
            for (int mi = 0; mi < 4; ++mi)
                ldsm4(ah[mi], aAddr + (uint32_t)mi * (16u * PITCH) + cOff);
            #pragma unroll
            for (int g = 0; g < 2; ++g)
                ldsm4(bh[g], bAddr + (uint32_t)g * (16u * PITCH) + cOff);
            #pragma unroll
            for (int mi = 0; mi < 4; ++mi)
                #pragma unroll
                for (int ni = 0; ni < 4; ++ni)
                    mma16816(acc[mi][ni], ah[mi], bh[ni >> 1][ni & 1], bh[ni >> 1][(ni & 1) + 2]);
        }
    }

    const int lr = lid >> 2;
    const int q2 = (lid & 3) * 2;
    #pragma unroll
    for (int mi = 0; mi < 4; ++mi) {
        #pragma unroll
        for (int half = 0; half < 2; ++half) {
            const int m = mBase + wm * 64 + mi * 16 + lr + half * 8;
            #pragma unroll
            for (int ni = 0; ni < 4; ++ni) {
                const int n = nBase + wn * 32 + ni * 8 + q2;
                *reinterpret_cast<float2*>(&C[(size_t)m * DHALF + n]) =
                    make_float2(acc[mi][ni][half * 2 + 0], acc[mi][ni][half * 2 + 1]);
            }
        }
    }
}

// ---------------------------------------------------------------------------
// Weight converter: 64x64 tiles, float4 loads, 32B/thread stores.
// Slot order s1W1,t1W1,s1W2,t1W2,s2W1,t2W1,s2W2,t2W2.
// ---------------------------------------------------------------------------
__global__ __launch_bounds__(256)
void convert_wT8(const float* __restrict__ W0, const float* __restrict__ W1,
                 const float* __restrict__ W2, const float* __restrict__ W3,
                 const float* __restrict__ W4, const float* __restrict__ W5,
                 const float* __restrict__ W6, const float* __restrict__ W7,
                 __half* __restrict__ T)
{
    const int z = blockIdx.z;
    const float* Ws[8] = {W0, W1, W2, W3, W4, W5, W6, W7};
    const float* W = Ws[z];
    const int typeW2 = (z >> 1) & 1;
    const int K = typeW2 ? HID : DHALF;
    const int N = typeW2 ? DHALF : HID;
    const int n0 = typeW2 ? blockIdx.y * 64 : blockIdx.x * 64;
    const int k0 = typeW2 ? blockIdx.x * 64 : blockIdx.y * 64;
    __half* t_out = T + (size_t)z * WSLOT;

    __shared__ float t[64][65];
    const int tid = threadIdx.x;
    const int lrow = tid >> 4;
    const int lc4  = (tid & 15) * 4;
    #pragma unroll
    for (int i = 0; i < 4; ++i) {
        const int rr = lrow + i * 16;
        float4 v = *reinterpret_cast<const float4*>(&W[(size_t)(k0 + rr) * N + n0 + lc4]);
        t[rr][lc4 + 0] = v.x;
        t[rr][lc4 + 1] = v.y;
        t[rr][lc4 + 2] = v.z;
        t[rr][lc4 + 3] = v.w;
    }
    __syncthreads();

    const int n  = tid >> 2;
    const int kc = (tid & 3) * 16;
    uint4 v0, v1;
    v0.x = pack_h2(__float2half(t[kc +  0][n]), __float2half(t[kc +  1][n]));
    v0.y = pack_h2(__float2half(t[kc +  2][n]), __float2half(t[kc +  3][n]));
    v0.z = pack_h2(__float2half(t[kc +  4][n]), __float2half(t[kc +  5][n]));
    v0.w = pack_h2(__float2half(t[kc +  6][n]), __float2half(t[kc +  7][n]));
    v1.x = pack_h2(__float2half(t[kc +  8][n]), __float2half(t[kc +  9][n]));
    v1.y = pack_h2(__float2half(t[kc + 10][n]), __float2half(t[kc + 11][n]));
    v1.z = pack_h2(__float2half(t[kc + 12][n]), __float2half(t[kc + 13][n]));
    v1.w = pack_h2(__float2half(t[kc + 14][n]), __float2half(t[kc + 15][n]));
    __half* dst = &t_out[(size_t)(n0 + n) * K + k0 + kc];
    *reinterpret_cast<uint4*>(dst)     = v0;
    *reinterpret_cast<uint4*>(dst + 8) = v1;
}

__global__ __launch_bounds__(256)
void convert_act(const float* __restrict__ x, __half* __restrict__ a)
{
    const int m = blockIdx.x;
    const int j = threadIdx.x * 4;
    float4 v = *reinterpret_cast<const float4*>(&x[(size_t)m * XCOLS + DHALF + j]);
    uint2 o = make_uint2(pack_h2(__float2half(v.x), __float2half(v.y)),
                         pack_h2(__float2half(v.z), __float2half(v.w)));
    *reinterpret_cast<uint2*>(&a[(size_t)m * DHALF + j]) = o;
}

// ---------------------------------------------------------------------------
// Coupling epilogue: sums K-split partials + bias, then couples.
// spre = s0+s1+bs; tval = t0+t1+bt; y = x*exp(tanh(spre)) + tval; logdet rowsum.
// ---------------------------------------------------------------------------
__global__ __launch_bounds__(256)
void ew_couple(const float* __restrict__ x,
               const float* __restrict__ s0p, const float* __restrict__ s1p,
               const float* __restrict__ t0p, const float* __restrict__ t1p,
               const float* __restrict__ bs,  const float* __restrict__ bt,
               float* __restrict__ y,
               float* __restrict__ logdet,
               __half* __restrict__ act,
               int xColOff, int yColOff, int addLogdet, int writeAct)
{
    const int m = blockIdx.x;
    const int j = threadIdx.x * 4;
    const size_t off = (size_t)m * DHALF + j;

    float4 sa = *reinterpret_cast<const float4*>(&s0p[off]);
    float4 sb4 = *reinterpret_cast<const float4*>(&s1p[off]);
    float4 ta = *reinterpret_cast<const float4*>(&t0p[off]);
    float4 tb = *reinterpret_cast<const float4*>(&t1p[off]);
    float4 bsv = *reinterpret_cast<const float4*>(&bs[j]);
    float4 btv = *reinterpret_cast<const float4*>(&bt[j]);
    float4 xv = *reinterpret_cast<const float4*>(&x[(size_t)m * XCOLS + xColOff + j]);

    float sp0 = sa.x + sb4.x + bsv.x;
    float sp1 = sa.y + sb4.y + bsv.y;
    float sp2 = sa.z + sb4.z + bsv.z;
    float sp3 = sa.w + sb4.w + bsv.w;
    float tv0 = ta.x + tb.x + btv.x;
    float tv1 = ta.y + tb.y + btv.y;
    float tv2 = ta.z + tb.z + btv.z;
    float tv3 = ta.w + tb.w + btv.w;

    float s0 = tanhf(sp0), s1 = tanhf(sp1), s2 = tanhf(sp2), s3 = tanhf(sp3);

    float4 o;
    o.x = xv.x * expf(s0) + tv0;
    o.y = xv.y * expf(s1) + tv1;
    o.z = xv.z * expf(s2) + tv2;
    o.w = xv.w * expf(s3) + tv3;
    *reinterpret_cast<float4*>(&y[(size_t)m * XCOLS + yColOff + j]) = o;

    if (writeAct) {
        uint2 av = make_uint2(pack_h2(__float2half(o.x), __float2half(o.y)),
                              pack_h2(__float2half(o.z), __float2half(o.w)));
        *reinterpret_cast<uint2*>(&act[off]) = av;
    }

    float lsum = s0 + s1 + s2 + s3;
    #pragma unroll
    for (int offs = 16; offs > 0; offs >>= 1)
        lsum += __shfl_xor_sync(0xFFFFFFFFu, lsum, offs);

    __shared__ float wsum[8];
    if ((threadIdx.x & 31) == 0) wsum[threadIdx.x >> 5] = lsum;
    __syncthreads();
    if (threadIdx.x == 0) {
        float tot = 0.0f;
        #pragma unroll
        for (int w = 0; w < 8; ++w) tot += wsum[w];
        if (addLogdet) logdet[m] += tot;
        else           logdet[m]  = tot;
    }
}

// ---------------------------------------------------------------------------
extern "C" void kernel_launch(void* const* d_in, const int* in_sizes, int n_in,
                              void* d_out, int out_size)
{
    (void)in_sizes; (void)n_in; (void)out_size;

    const float* x = (const float*)d_in[0];
    const float* Wslot[8] = { (const float*)d_in[1],  (const float*)d_in[5],
                              (const float*)d_in[3],  (const float*)d_in[7],
                              (const float*)d_in[9],  (const float*)d_in[13],
                              (const float*)d_in[11], (const float*)d_in[15] };
    const float* s1_b1 = (const float*)d_in[2];
    const float* s1_b2 = (const float*)d_in[4];
    const float* t1_b1 = (const float*)d_in[6];
    const float* t1_b2 = (const float*)d_in[8];
    const float* s2_b1 = (const float*)d_in[10];
    const float* s2_b2 = (const float*)d_in[12];
    const float* t2_b1 = (const float*)d_in[14];
    const float* t2_b2 = (const float*)d_in[16];

    float* y      = (float*)d_out;
    float* logdet = y + (size_t)BATCH * XCOLS;

    __half *act, *hid, *wt;
    float *s0b, *s1b, *t0b, *t1b;
    cudaGetSymbolAddress((void**)&act, g_act);
    cudaGetSymbolAddress((void**)&hid, g_hid);
    cudaGetSymbolAddress((void**)&wt,  g_wt);
    cudaGetSymbolAddress((void**)&s0b, g_s0);
    cudaGetSymbolAddress((void**)&s1b, g_s1);
    cudaGetSymbolAddress((void**)&t0b, g_t0);
    cudaGetSymbolAddress((void**)&t1b, g_t1);

    cudaFuncSetAttribute(gemm_l1, cudaFuncAttributeMaxDynamicSharedMemorySize, SMEM_BYTES);
    cudaFuncSetAttribute(gemm_l2, cudaFuncAttributeMaxDynamicSharedMemorySize, SMEM_BYTES);

    convert_wT8<<<dim3(64, 16, 8), 256>>>(Wslot[0], Wslot[1], Wslot[2], Wslot[3],
                                          Wslot[4], Wslot[5], Wslot[6], Wslot[7], wt);
    convert_act<<<BATCH, 256>>>(x, act);

    dim3 gridL1(L1_N / 128, BATCH / 128);        // 64 x 64
    dim3 gridL2(DHALF / 128, BATCH / 128, 4);    // 8 x 64 x 4 = 2048 CTAs

    // phase 1
    gemm_l1<<<gridL1, 256, SMEM_BYTES>>>(act, wt + 0 * WSLOT, s1_b1, t1_b1, hid);
    gemm_l2<<<gridL2, 256, SMEM_BYTES>>>(hid, wt + 2 * WSLOT, s0b, s1b, t0b, t1b);
    ew_couple<<<BATCH, 256>>>(x, s0b, s1b, t0b, t1b, s1_b2, t1_b2, y, logdet, act, 0, 0, 0, 1);

    // phase 2
    gemm_l1<<<gridL1, 256, SMEM_BYTES>>>(act, wt + 4 * WSLOT, s2_b1, t2_b1, hid);
    gemm_l2<<<gridL2, 256, SMEM_BYTES>>>(hid, wt + 6 * WSLOT, s0b, s1b, t0b, t1b);
    ew_couple<<<BATCH, 256>>>(x, s0b, s1b, t0b, t1b, s2_b2, t2_b2, y, logdet, nullptr, DHALF, DHALF, 1, 0);
}

// round 15
// speedup vs baseline: 1.5040x; 1.5040x over previous
#include <cuda_runtime.h>
#include <cuda_fp16.h>
#include <cstdint>
#include <math.h>

#define BATCH 8192
#define DHALF 1024
#define HID   4096
#define XCOLS 2048
#define WSLOT ((size_t)DHALF * HID)

// ---------------- scratch (device globals: allocation-free rule) -----------
__device__ __half g_act[(size_t)BATCH * DHALF];
__device__ __half g_hid[(size_t)BATCH * 2 * HID];   // s cols [0,4096), t cols [4096,8192)
__device__ __half g_wt[8 * WSLOT];
__device__ float g_s[(size_t)BATCH * DHALF];
__device__ float g_t[(size_t)BATCH * DHALF];

// ---------------- helpers ----------------------------------------------
__device__ __forceinline__ uint32_t smem_u32(const void* p) {
    uint32_t a;
    asm("{ .reg .u64 t; cvta.to.shared.u64 t, %1; cvt.u32.u64 %0, t; }" : "=r"(a) : "l"(p));
    return a;
}
__device__ __forceinline__ void cp16(uint32_t s, const void* g) {
    asm volatile("cp.async.cg.shared.global [%0], [%1], 16;" :: "r"(s), "l"(g));
}
__device__ __forceinline__ uint32_t pack_h2(__half a, __half b) {
    __half2 t = __halves2half2(a, b);
    return *reinterpret_cast<uint32_t*>(&t);
}
__device__ __forceinline__ void mma16816(float* d, const uint32_t* a, uint32_t b0, uint32_t b1) {
    asm volatile(
        "mma.sync.aligned.m16n8k16.row.col.f32.f16.f16.f32 "
        "{%0,%1,%2,%3}, {%4,%5,%6,%7}, {%8,%9}, {%0,%1,%2,%3};"
        : "+f"(d[0]), "+f"(d[1]), "+f"(d[2]), "+f"(d[3])
        : "r"(a[0]), "r"(a[1]), "r"(a[2]), "r"(a[3]), "r"(b0), "r"(b1));
}
__device__ __forceinline__ void ldsm4(uint32_t* r, uint32_t addr) {
    asm volatile("ldmatrix.sync.aligned.m8n8.x4.shared.b16 {%0,%1,%2,%3}, [%4];"
        : "=r"(r[0]), "=r"(r[1]), "=r"(r[2]), "=r"(r[3]) : "r"(addr));
}

#define PITCH 144u

// ---------------------------------------------------------------------------
// Layer-1 GEMM (merged s&t): hid[m, 0..8191] = relu(act @ [Ws|Wt]^T + [bs|bt])
// BM=128, BN=128, BK=64, 3 stages, 2 CTAs/SM, 8 warps (2m x 4n), warp 64x32.
// ---------------------------------------------------------------------------
#define L1_K 1024
#define L1_N 8192
#define L1_TILEB (128u * PITCH)              // 18432
#define L1_STAGEB (2u * L1_TILEB)            // 36864
#define L1_SMEM (3u * L1_STAGEB)             // 110592

__global__ __launch_bounds__(256, 2)
void gemm_l1(const __half* __restrict__ A,
             const __half* __restrict__ B,
             const float* __restrict__ bias0,
             const float* __restrict__ bias1,
             __half* __restrict__ Ch)
{
    extern __shared__ char smem[];
    const uint32_t sb = smem_u32(smem);
    const int tid = threadIdx.x;
    const int wid = tid >> 5;
    const int lid = tid & 31;
    const int wm = wid & 1;
    const int wn = wid >> 1;
    const int mBase = blockIdx.y * 128;
    const int nBase = blockIdx.x * 128;
    const float* __restrict__ bb = (nBase < HID) ? bias0 : bias1;

    auto load_stage = [&](int stage, int k0) {
        const uint32_t st = sb + stage * L1_STAGEB;
        #pragma unroll
        for (int j = 0; j < 4; ++j) {
            int i = tid + 256 * j;
            int r = i >> 3, c = i & 7;
            uint32_t off = (uint32_t)r * PITCH + (uint32_t)c * 16u;
            cp16(st + off,             A + (size_t)(mBase + r) * L1_K + k0 + c * 8);
            cp16(st + L1_TILEB + off,  B + (size_t)(nBase + r) * L1_K + k0 + c * 8);
        }
        asm volatile("cp.async.commit_group;" ::: "memory");
    };

    float acc[4][4][4];
    #pragma unroll
    for (int i = 0; i < 4; ++i)
        #pragma unroll
        for (int j = 0; j < 4; ++j)
            #pragma unroll
            for (int q = 0; q < 4; ++q) acc[i][j][q] = 0.f;

    const int NC = L1_K / 64;
    load_stage(0, 0);
    load_stage(1, 64);

    const int lr16 = lid & 15;
    const uint32_t lcol = (uint32_t)(lid >> 4) * 16u;

    for (int c = 0; c < NC; ++c) {
        const int s = c % 3;
        asm volatile("cp.async.wait_group 1;" ::: "memory");
        __syncthreads();
        if (c + 2 < NC) load_stage((c + 2) % 3, (c + 2) * 64);

        const uint32_t st = sb + s * L1_STAGEB;
        const uint32_t aAddr = st + (uint32_t)(wm * 64 + lr16) * PITCH + lcol;
        const uint32_t bAddr = st + L1_TILEB + (uint32_t)(wn * 32 + lr16) * PITCH + lcol;

        #pragma unroll
        for (int kb = 0; kb < 4; ++kb) {
            const uint32_t cOff = (uint32_t)kb * 32u;
            uint32_t ah[4][4], bh[2][4];
            #pragma unroll
            for (int mi = 0; mi < 4; ++mi)
                ldsm4(ah[mi], aAddr + (uint32_t)mi * (16u * PITCH) + cOff);
            #pragma unroll
            for (int g = 0; g < 2; ++g)
                ldsm4(bh[g], bAddr + (uint32_t)g * (16u * PITCH) + cOff);
            #pragma unroll
            for (int mi = 0; mi < 4; ++mi)
                #pragma unroll
                for (int ni = 0; ni < 4; ++ni)
                    mma16816(acc[mi][ni], ah[mi], bh[ni >> 1][ni & 1], bh[ni >> 1][(ni & 1) + 2]);
        }
    }

    const int lr = lid >> 2;
    const int q2 = (lid & 3) * 2;
    #pragma unroll
    for (int mi = 0; mi < 4; ++mi) {
        #pragma unroll
        for (int half = 0; half < 2; ++half) {
            const int m = mBase + wm * 64 + mi * 16 + lr + half * 8;
            #pragma unroll
            for (int ni = 0; ni < 4; ++ni) {
                const int n = nBase + wn * 32 + ni * 8 + q2;
                const int nb = n & (HID - 1);
                float v0 = fmaxf(acc[mi][ni][half * 2 + 0] + bb[nb],     0.f);
                float v1 = fmaxf(acc[mi][ni][half * 2 + 1] + bb[nb + 1], 0.f);
                *reinterpret_cast<uint32_t*>(&Ch[(size_t)m * L1_N + n]) =
                    pack_h2(__float2half(v0), __float2half(v1));
            }
        }
    }
}

// ---------------------------------------------------------------------------
// Layer-2 GEMM, z-batched: C_z = hid[:, z*4096+k] @ Wz^T + bias_z (fp32 out)
// BM=64, BN=128, BK=64, 4 stages, 2 CTAs/SM, warp tile 32x32. K=4096.
// ---------------------------------------------------------------------------
#define L2_K 4096
#define L2_ATILE (64u * PITCH)               // 9216
#define L2_BTILE (128u * PITCH)              // 18432
#define L2_STAGEB (L2_ATILE + L2_BTILE)      // 27648
#define L2_SMEM (4u * L2_STAGEB)             // 110592

__global__ __launch_bounds__(256, 2)
void gemm_l2(const __half* __restrict__ Ab,
             const __half* __restrict__ Wb,
             const float* __restrict__ bias0, const float* __restrict__ bias1,
             float* __restrict__ C0, float* __restrict__ C1)
{
    extern __shared__ char smem[];
    const uint32_t sb = smem_u32(smem);
    const int tid = threadIdx.x;
    const int wid = tid >> 5;
    const int lid = tid & 31;
    const int wm = wid & 1;
    const int wn = wid >> 1;
    const int z  = blockIdx.z;
    const int mBase = blockIdx.y * 64;
    const int nBase = blockIdx.x * 128;

    const __half* __restrict__ A = Ab + (size_t)z * HID;
    const __half* __restrict__ B = Wb + (size_t)z * WSLOT;
    const float* __restrict__ bias = z ? bias1 : bias0;
    float* __restrict__ C = z ? C1 : C0;

    auto load_stage = [&](int stage, int k0) {
        const uint32_t st = sb + stage * L2_STAGEB;
        #pragma unroll
        for (int j = 0; j < 2; ++j) {
            int i = tid + 256 * j;
            int r = i >> 3, c = i & 7;
            uint32_t off = (uint32_t)r * PITCH + (uint32_t)c * 16u;
            cp16(st + off, A + (size_t)(mBase + r) * (2 * HID) + k0 + c * 8);
        }
        #pragma unroll
        for (int j = 0; j < 4; ++j) {
            int i = tid + 256 * j;
            int r = i >> 3, c = i & 7;
            uint32_t off = (uint32_t)r * PITCH + (uint32_t)c * 16u;
            cp16(st + L2_ATILE + off, B + (size_t)(nBase + r) * L2_K + k0 + c * 8);
        }
        asm volatile("cp.async.commit_group;" ::: "memory");
    };

    float acc[2][4][4];
    #pragma unroll
    for (int i = 0; i < 2; ++i)
        #pragma unroll
        for (int j = 0; j < 4; ++j)
            #pragma unroll
            for (int q = 0; q < 4; ++q) acc[i][j][q] = 0.f;

    const int NC = L2_K / 64;
    load_stage(0, 0);
    load_stage(1, 64);
    load_stage(2, 128);

    const int lr16 = lid & 15;
    const uint32_t lcol = (uint32_t)(lid >> 4) * 16u;

    for (int c = 0; c < NC; ++c) {
        const int s = c & 3;
        asm volatile("cp.async.wait_group 2;" ::: "memory");
        __syncthreads();
        if (c + 3 < NC) load_stage((c + 3) & 3, (c + 3) * 64);

        const uint32_t st = sb + s * L2_STAGEB;
        const uint32_t aAddr = st + (uint32_t)(wm * 32 + lr16) * PITCH + lcol;
        const uint32_t bAddr = st + L2_ATILE + (uint32_t)(wn * 32 + lr16) * PITCH + lcol;

        #pragma unroll
        for (int kb = 0; kb < 4; ++kb) {
            const uint32_t cOff = (uint32_t)kb * 32u;
            uint32_t ah[2][4], bh[2][4];
            #pragma unroll
            for (int mi = 0; mi < 2; ++mi)
                ldsm4(ah[mi], aAddr + (uint32_t)mi * (16u * PITCH) + cOff);
            #pragma unroll
            for (int g = 0; g < 2; ++g)
                ldsm4(bh[g], bAddr + (uint32_t)g * (16u * PITCH) + cOff);
            #pragma unroll
            for (int mi = 0; mi < 2; ++mi)
                #pragma unroll
                for (int ni = 0; ni < 4; ++ni)
                    mma16816(acc[mi][ni], ah[mi], bh[ni >> 1][ni & 1], bh[ni >> 1][(ni & 1) + 2]);
        }
    }

    const int lr = lid >> 2;
    const int q2 = (lid & 3) * 2;
    #pragma unroll
    for (int mi = 0; mi < 2; ++mi) {
        #pragma unroll
        for (int half = 0; half < 2; ++half) {
            const int m = mBase + wm * 32 + mi * 16 + lr + half * 8;
            #pragma unroll
            for (int ni = 0; ni < 4; ++ni) {
                const int n = nBase + wn * 32 + ni * 8 + q2;
                float v0 = acc[mi][ni][half * 2 + 0] + bias[n];
                float v1 = acc[mi][ni][half * 2 + 1] + bias[n + 1];
                *reinterpret_cast<float2*>(&C[(size_t)m * DHALF + n]) = make_float2(v0, v1);
            }
        }
    }
}

// ---------------------------------------------------------------------------
// Fused converter: z=0..7 -> weight transpose+fp16 (64x64 tiles);
// z=8 -> x2 slice -> fp16 act. Each z=8 block: 8 rows x full 1024 cols
// (4 column strides of 256). Slot order s1W1,t1W1,s1W2,t1W2,s2W1,t2W1,s2W2,t2W2.
// ---------------------------------------------------------------------------
__global__ __launch_bounds__(256)
void convert_all(const float* __restrict__ W0, const float* __restrict__ W1,
                 const float* __restrict__ W2, const float* __restrict__ W3,
                 const float* __restrict__ W4, const float* __restrict__ W5,
                 const float* __restrict__ W6, const float* __restrict__ W7,
                 const float* __restrict__ x,
                 __half* __restrict__ T, __half* __restrict__ act)
{
    const int z = blockIdx.z;
    if (z == 8) {
        const int b = blockIdx.y * 64 + blockIdx.x;       // 0..1023
        const int m = b * 8 + (threadIdx.x >> 5);         // 8 rows per block
        const int jBase = (threadIdx.x & 31) * 8;         // lane column base
        #pragma unroll
        for (int it = 0; it < 4; ++it) {
            const int j = jBase + it * 256;               // covers 0..1023
            float4 v0 = *reinterpret_cast<const float4*>(&x[(size_t)m * XCOLS + DHALF + j]);
            float4 v1 = *reinterpret_cast<const float4*>(&x[(size_t)m * XCOLS + DHALF + j + 4]);
            uint4 o;
            o.x = pack_h2(__float2half(v0.x), __float2half(v0.y));
            o.y = pack_h2(__float2half(v0.z), __float2half(v0.w));
            o.z = pack_h2(__float2half(v1.x), __float2half(v1.y));
            o.w = pack_h2(__float2half(v1.z), __float2half(v1.w));
            *reinterpret_cast<uint4*>(&act[(size_t)m * DHALF + j]) = o;
        }
        return;
    }

    const float* Ws[8] = {W0, W1, W2, W3, W4, W5, W6, W7};
    const float* W = Ws[z];
    const int typeW2 = (z >> 1) & 1;
    const int K = typeW2 ? HID : DHALF;
    const int N = typeW2 ? DHALF : HID;
    const int n0 = typeW2 ? blockIdx.y * 64 : blockIdx.x * 64;
    const int k0 = typeW2 ? blockIdx.x * 64 : blockIdx.y * 64;
    __half* t_out = T + (size_t)z * WSLOT;

    __shared__ float t[64][65];
    const int tid = threadIdx.x;
    const int lrow = tid >> 4;
    const int lc4  = (tid & 15) * 4;
    #pragma unroll
    for (int i = 0; i < 4; ++i) {
        const int rr = lrow + i * 16;
        float4 v = *reinterpret_cast<const float4*>(&W[(size_t)(k0 + rr) * N + n0 + lc4]);
        t[rr][lc4 + 0] = v.x;
        t[rr][lc4 + 1] = v.y;
        t[rr][lc4 + 2] = v.z;
        t[rr][lc4 + 3] = v.w;
    }
    __syncthreads();

    const int n  = tid >> 2;
    const int kc = (tid & 3) * 16;
    uint4 v0, v1;
    v0.x = pack_h2(__float2half(t[kc +  0][n]), __float2half(t[kc +  1][n]));
    v0.y = pack_h2(__float2half(t[kc +  2][n]), __float2half(t[kc +  3][n]));
    v0.z = pack_h2(__float2half(t[kc +  4][n]), __float2half(t[kc +  5][n]));
    v0.w = pack_h2(__float2half(t[kc +  6][n]), __float2half(t[kc +  7][n]));
    v1.x = pack_h2(__float2half(t[kc +  8][n]), __float2half(t[kc +  9][n]));
    v1.y = pack_h2(__float2half(t[kc + 10][n]), __float2half(t[kc + 11][n]));
    v1.z = pack_h2(__float2half(t[kc + 12][n]), __float2half(t[kc + 13][n]));
    v1.w = pack_h2(__float2half(t[kc + 14][n]), __float2half(t[kc + 15][n]));
    __half* dst = &t_out[(size_t)(n0 + n) * K + k0 + kc];
    *reinterpret_cast<uint4*>(dst)     = v0;
    *reinterpret_cast<uint4*>(dst + 8) = v1;
}

// ---------------------------------------------------------------------------
// Coupling epilogue
// ---------------------------------------------------------------------------
__global__ __launch_bounds__(256)
void ew_couple(const float* __restrict__ x,
               const float* __restrict__ spre,
               const float* __restrict__ tval,
               float* __restrict__ y,
               float* __restrict__ logdet,
               __half* __restrict__ act,
               int xColOff, int yColOff, int addLogdet, int writeAct)
{
    const int m = blockIdx.x;
    const int j = threadIdx.x * 4;

    float4 sp = *reinterpret_cast<const float4*>(&spre[(size_t)m * DHALF + j]);
    float4 tv = *reinterpret_cast<const float4*>(&tval[(size_t)m * DHALF + j]);
    float4 xv = *reinterpret_cast<const float4*>(&x[(size_t)m * XCOLS + xColOff + j]);

    float s0 = tanhf(sp.x), s1 = tanhf(sp.y), s2 = tanhf(sp.z), s3 = tanhf(sp.w);

    float4 o;
    o.x = xv.x * expf(s0) + tv.x;
    o.y = xv.y * expf(s1) + tv.y;
    o.z = xv.z * expf(s2) + tv.z;
    o.w = xv.w * expf(s3) + tv.w;
    *reinterpret_cast<float4*>(&y[(size_t)m * XCOLS + yColOff + j]) = o;

    if (writeAct) {
        uint2 av = make_uint2(pack_h2(__float2half(o.x), __float2half(o.y)),
                              pack_h2(__float2half(o.z), __float2half(o.w)));
        *reinterpret_cast<uint2*>(&act[(size_t)m * DHALF + j]) = av;
    }

    float lsum = s0 + s1 + s2 + s3;
    #pragma unroll
    for (int off = 16; off > 0; off >>= 1)
        lsum += __shfl_xor_sync(0xFFFFFFFFu, lsum, off);

    __shared__ float wsum[8];
    if ((threadIdx.x & 31) == 0) wsum[threadIdx.x >> 5] = lsum;
    __syncthreads();
    if (threadIdx.x == 0) {
        float tot = 0.0f;
        #pragma unroll
        for (int w = 0; w < 8; ++w) tot += wsum[w];
        if (addLogdet) logdet[m] += tot;
        else           logdet[m]  = tot;
    }
}

// ---------------------------------------------------------------------------
extern "C" void kernel_launch(void* const* d_in, const int* in_sizes, int n_in,
                              void* d_out, int out_size)
{
    (void)in_sizes; (void)n_in; (void)out_size;

    const float* x = (const float*)d_in[0];
    const float* Wslot[8] = { (const float*)d_in[1],  (const float*)d_in[5],
                              (const float*)d_in[3],  (const float*)d_in[7],
                              (const float*)d_in[9],  (const float*)d_in[13],
                              (const float*)d_in[11], (const float*)d_in[15] };
    const float* s1_b1 = (const float*)d_in[2];
    const float* s1_b2 = (const float*)d_in[4];
    const float* t1_b1 = (const float*)d_in[6];
    const float* t1_b2 = (const float*)d_in[8];
    const float* s2_b1 = (const float*)d_in[10];
    const float* s2_b2 = (const float*)d_in[12];
    const float* t2_b1 = (const float*)d_in[14];
    const float* t2_b2 = (const float*)d_in[16];

    float* y      = (float*)d_out;
    float* logdet = y + (size_t)BATCH * XCOLS;

    __half *act, *hid, *wt;
    float *sbuf, *tbuf;
    cudaGetSymbolAddress((void**)&act, g_act);
    cudaGetSymbolAddress((void**)&hid, g_hid);
    cudaGetSymbolAddress((void**)&wt,  g_wt);
    cudaGetSymbolAddress((void**)&sbuf, g_s);
    cudaGetSymbolAddress((void**)&tbuf, g_t);

    cudaFuncSetAttribute(gemm_l1, cudaFuncAttributeMaxDynamicSharedMemorySize, L1_SMEM);
    cudaFuncSetAttribute(gemm_l2, cudaFuncAttributeMaxDynamicSharedMemorySize, L2_SMEM);

    convert_all<<<dim3(64, 16, 9), 256>>>(Wslot[0], Wslot[1], Wslot[2], Wslot[3],
                                          Wslot[4], Wslot[5], Wslot[6], Wslot[7],
                                          x, wt, act);

    dim3 gridL1(L1_N / 128, BATCH / 128);        // 64 x 64
    dim3 gridL2(DHALF / 128, BATCH / 64, 2);     // 8 x 128 x 2

    // phase 1
    gemm_l1<<<gridL1, 256, L1_SMEM>>>(act, wt + 0 * WSLOT, s1_b1, t1_b1, hid);
    gemm_l2<<<gridL2, 256, L2_SMEM>>>(hid, wt + 2 * WSLOT, s1_b2, t1_b2, sbuf, tbuf);
    ew_couple<<<BATCH, 256>>>(x, sbuf, tbuf, y, logdet, act, 0, 0, 0, 1);

    // phase 2
    gemm_l1<<<gridL1, 256, L1_SMEM>>>(act, wt + 4 * WSLOT, s2_b1, t2_b1, hid);
    gemm_l2<<<gridL2, 256, L2_SMEM>>>(hid, wt + 6 * WSLOT, s2_b2, t2_b2, sbuf, tbuf);
    ew_couple<<<BATCH, 256>>>(x, sbuf, tbuf, y, logdet, nullptr, DHALF, DHALF, 1, 0);
}

// round 16
// speedup vs baseline: 1.5614x; 1.0382x over previous
#include <cuda_runtime.h>
#include <cuda_fp16.h>
#include <cstdint>
#include <math.h>

#define BATCH 8192
#define DHALF 1024
#define HID   4096
#define XCOLS 2048
#define WSLOT ((size_t)DHALF * HID)

// ---------------- scratch (device globals: allocation-free rule) -----------
__device__ __half g_act[(size_t)BATCH * DHALF];
__device__ __half g_hid[(size_t)BATCH * 2 * HID];   // s cols [0,4096), t cols [4096,8192)
__device__ __half g_wt[8 * WSLOT];
__device__ float g_s[(size_t)BATCH * DHALF];
__device__ float g_t[(size_t)BATCH * DHALF];

// ---------------- helpers ----------------------------------------------
__device__ __forceinline__ uint32_t smem_u32(const void* p) {
    uint32_t a;
    asm("{ .reg .u64 t; cvta.to.shared.u64 t, %1; cvt.u32.u64 %0, t; }" : "=r"(a) : "l"(p));
    return a;
}
__device__ __forceinline__ void cp16(uint32_t s, const void* g) {
    asm volatile("cp.async.cg.shared.global [%0], [%1], 16;" :: "r"(s), "l"(g));
}
__device__ __forceinline__ uint32_t pack_h2(__half a, __half b) {
    __half2 t = __halves2half2(a, b);
    return *reinterpret_cast<uint32_t*>(&t);
}
__device__ __forceinline__ void mma16816(float* d, const uint32_t* a, uint32_t b0, uint32_t b1) {
    asm volatile(
        "mma.sync.aligned.m16n8k16.row.col.f32.f16.f16.f32 "
        "{%0,%1,%2,%3}, {%4,%5,%6,%7}, {%8,%9}, {%0,%1,%2,%3};"
        : "+f"(d[0]), "+f"(d[1]), "+f"(d[2]), "+f"(d[3])
        : "r"(a[0]), "r"(a[1]), "r"(a[2]), "r"(a[3]), "r"(b0), "r"(b1));
}
__device__ __forceinline__ void ldsm4(uint32_t* r, uint32_t addr) {
    asm volatile("ldmatrix.sync.aligned.m8n8.x4.shared.b16 {%0,%1,%2,%3}, [%4];"
        : "=r"(r[0]), "=r"(r[1]), "=r"(r[2]), "=r"(r[3]) : "r"(addr));
}

#define PITCH 144u

// ---------------------------------------------------------------------------
// Layer-1 GEMM (merged s&t): hid[m, 0..8191] = relu(act @ [Ws|Wt]^T + [bs|bt])
// BM=128, BN=128, BK=64, 3 stages, 2 CTAs/SM, 8 warps (2m x 4n), warp 64x32.
// ---------------------------------------------------------------------------
#define L1_K 1024
#define L1_N 8192
#define L1_TILEB (128u * PITCH)              // 18432
#define L1_STAGEB (2u * L1_TILEB)            // 36864
#define L1_SMEM (3u * L1_STAGEB)             // 110592

__global__ __launch_bounds__(256, 2)
void gemm_l1(const __half* __restrict__ A,
             const __half* __restrict__ B,
             const float* __restrict__ bias0,
             const float* __restrict__ bias1,
             __half* __restrict__ Ch)
{
    extern __shared__ char smem[];
    const uint32_t sb = smem_u32(smem);
    const int tid = threadIdx.x;
    const int wid = tid >> 5;
    const int lid = tid & 31;
    const int wm = wid & 1;
    const int wn = wid >> 1;
    const int mBase = blockIdx.y * 128;
    const int nBase = blockIdx.x * 128;
    const float* __restrict__ bb = (nBase < HID) ? bias0 : bias1;

    auto load_stage = [&](int stage, int k0) {
        const uint32_t st = sb + stage * L1_STAGEB;
        #pragma unroll
        for (int j = 0; j < 4; ++j) {
            int i = tid + 256 * j;
            int r = i >> 3, c = i & 7;
            uint32_t off = (uint32_t)r * PITCH + (uint32_t)c * 16u;
            cp16(st + off,             A + (size_t)(mBase + r) * L1_K + k0 + c * 8);
            cp16(st + L1_TILEB + off,  B + (size_t)(nBase + r) * L1_K + k0 + c * 8);
        }
        asm volatile("cp.async.commit_group;" ::: "memory");
    };

    float acc[4][4][4];
    #pragma unroll
    for (int i = 0; i < 4; ++i)
        #pragma unroll
        for (int j = 0; j < 4; ++j)
            #pragma unroll
            for (int q = 0; q < 4; ++q) acc[i][j][q] = 0.f;

    const int NC = L1_K / 64;
    load_stage(0, 0);
    load_stage(1, 64);

    const int lr16 = lid & 15;
    const uint32_t lcol = (uint32_t)(lid >> 4) * 16u;

    for (int c = 0; c < NC; ++c) {
        const int s = c % 3;
        asm volatile("cp.async.wait_group 1;" ::: "memory");
        __syncthreads();
        if (c + 2 < NC) load_stage((c + 2) % 3, (c + 2) * 64);

        const uint32_t st = sb + s * L1_STAGEB;
        const uint32_t aAddr = st + (uint32_t)(wm * 64 + lr16) * PITCH + lcol;
        const uint32_t bAddr = st + L1_TILEB + (uint32_t)(wn * 32 + lr16) * PITCH + lcol;

        #pragma unroll
        for (int kb = 0; kb < 4; ++kb) {
            const uint32_t cOff = (uint32_t)kb * 32u;
            uint32_t ah[4][4], bh[2][4];
            #pragma unroll
            for (int mi = 0; mi < 4; ++mi)
                ldsm4(ah[mi], aAddr + (uint32_t)mi * (16u * PITCH) + cOff);
            #pragma unroll
            for (int g = 0; g < 2; ++g)
                ldsm4(bh[g], bAddr + (uint32_t)g * (16u * PITCH) + cOff);
            #pragma unroll
            for (int mi = 0; mi < 4; ++mi)
                #pragma unroll
                for (int ni = 0; ni < 4; ++ni)
                    mma16816(acc[mi][ni], ah[mi], bh[ni >> 1][ni & 1], bh[ni >> 1][(ni & 1) + 2]);
        }
    }

    const int lr = lid >> 2;
    const int q2 = (lid & 3) * 2;
    #pragma unroll
    for (int mi = 0; mi < 4; ++mi) {
        #pragma unroll
        for (int half = 0; half < 2; ++half) {
            const int m = mBase + wm * 64 + mi * 16 + lr + half * 8;
            #pragma unroll
            for (int ni = 0; ni < 4; ++ni) {
                const int n = nBase + wn * 32 + ni * 8 + q2;
                const int nb = n & (HID - 1);
                float v0 = fmaxf(acc[mi][ni][half * 2 + 0] + bb[nb],     0.f);
                float v1 = fmaxf(acc[mi][ni][half * 2 + 1] + bb[nb + 1], 0.f);
                *reinterpret_cast<uint32_t*>(&Ch[(size_t)m * L1_N + n]) =
                    pack_h2(__float2half(v0), __float2half(v1));
            }
        }
    }
}

// ---------------------------------------------------------------------------
// Layer-2 GEMM, z-batched: C_z = hid[:, z*4096+k] @ Wz^T + bias_z (fp32 out)
// BM=64, BN=128, BK=64, 2 stages, 3 CTAs/SM, warp tile 32x32. K=4096.
// ---------------------------------------------------------------------------
#define L2_K 4096
#define L2_ATILE (64u * PITCH)               // 9216
#define L2_BTILE (128u * PITCH)              // 18432
#define L2_STAGEB (L2_ATILE + L2_BTILE)      // 27648
#define L2_SMEM (2u * L2_STAGEB)             // 55296

__global__ __launch_bounds__(256, 3)
void gemm_l2(const __half* __restrict__ Ab,
             const __half* __restrict__ Wb,
             const float* __restrict__ bias0, const float* __restrict__ bias1,
             float* __restrict__ C0, float* __restrict__ C1)
{
    extern __shared__ char smem[];
    const uint32_t sb = smem_u32(smem);
    const int tid = threadIdx.x;
    const int wid = tid >> 5;
    const int lid = tid & 31;
    const int wm = wid & 1;
    const int wn = wid >> 1;
    const int z  = blockIdx.z;
    const int mBase = blockIdx.y * 64;
    const int nBase = blockIdx.x * 128;

    const __half* __restrict__ A = Ab + (size_t)z * HID;
    const __half* __restrict__ B = Wb + (size_t)z * WSLOT;
    const float* __restrict__ bias = z ? bias1 : bias0;
    float* __restrict__ C = z ? C1 : C0;

    auto load_stage = [&](int stage, int k0) {
        const uint32_t st = sb + stage * L2_STAGEB;
        #pragma unroll
        for (int j = 0; j < 2; ++j) {
            int i = tid + 256 * j;
            int r = i >> 3, c = i & 7;
            uint32_t off = (uint32_t)r * PITCH + (uint32_t)c * 16u;
            cp16(st + off, A + (size_t)(mBase + r) * (2 * HID) + k0 + c * 8);
        }
        #pragma unroll
        for (int j = 0; j < 4; ++j) {
            int i = tid + 256 * j;
            int r = i >> 3, c = i & 7;
            uint32_t off = (uint32_t)r * PITCH + (uint32_t)c * 16u;
            cp16(st + L2_ATILE + off, B + (size_t)(nBase + r) * L2_K + k0 + c * 8);
        }
        asm volatile("cp.async.commit_group;" ::: "memory");
    };

    float acc[2][4][4];
    #pragma unroll
    for (int i = 0; i < 2; ++i)
        #pragma unroll
        for (int j = 0; j < 4; ++j)
            #pragma unroll
            for (int q = 0; q < 4; ++q) acc[i][j][q] = 0.f;

    const int NC = L2_K / 64;
    load_stage(0, 0);                 // prefetch chunk 0

    const int lr16 = lid & 15;
    const uint32_t lcol = (uint32_t)(lid >> 4) * 16u;

    for (int c = 0; c < NC; ++c) {
        const int s = c & 1;
        asm volatile("cp.async.wait_group 0;" ::: "memory");
        __syncthreads();              // data visible + stage s^1 free

        if (c + 1 < NC) load_stage(s ^ 1, (c + 1) * 64);

        const uint32_t st = sb + s * L2_STAGEB;
        const uint32_t aAddr = st + (uint32_t)(wm * 32 + lr16) * PITCH + lcol;
        const uint32_t bAddr = st + L2_ATILE + (uint32_t)(wn * 32 + lr16) * PITCH + lcol;

        #pragma unroll
        for (int kb = 0; kb < 4; ++kb) {
            const uint32_t cOff = (uint32_t)kb * 32u;
            uint32_t ah[2][4], bh[2][4];
            #pragma unroll
            for (int mi = 0; mi < 2; ++mi)
                ldsm4(ah[mi], aAddr + (uint32_t)mi * (16u * PITCH) + cOff);
            #pragma unroll
            for (int g = 0; g < 2; ++g)
                ldsm4(bh[g], bAddr + (uint32_t)g * (16u * PITCH) + cOff);
            #pragma unroll
            for (int mi = 0; mi < 2; ++mi)
                #pragma unroll
                for (int ni = 0; ni < 4; ++ni)
                    mma16816(acc[mi][ni], ah[mi], bh[ni >> 1][ni & 1], bh[ni >> 1][(ni & 1) + 2]);
        }
    }

    const int lr = lid >> 2;
    const int q2 = (lid & 3) * 2;
    #pragma unroll
    for (int mi = 0; mi < 2; ++mi) {
        #pragma unroll
        for (int half = 0; half < 2; ++half) {
            const int m = mBase + wm * 32 + mi * 16 + lr + half * 8;
            #pragma unroll
            for (int ni = 0; ni < 4; ++ni) {
                const int n = nBase + wn * 32 + ni * 8 + q2;
                float v0 = acc[mi][ni][half * 2 + 0] + bias[n];
                float v1 = acc[mi][ni][half * 2 + 1] + bias[n + 1];
                *reinterpret_cast<float2*>(&C[(size_t)m * DHALF + n]) = make_float2(v0, v1);
            }
        }
    }
}

// ---------------------------------------------------------------------------
// Fused converter: z=0..7 -> weight transpose+fp16 (64x64 tiles);
// z=8 -> x2 slice -> fp16 act (8 rows x 1024 cols per block).
// Slot order s1W1,t1W1,s1W2,t1W2,s2W1,t2W1,s2W2,t2W2.
// ---------------------------------------------------------------------------
__global__ __launch_bounds__(256)
void convert_all(const float* __restrict__ W0, const float* __restrict__ W1,
                 const float* __restrict__ W2, const float* __restrict__ W3,
                 const float* __restrict__ W4, const float* __restrict__ W5,
                 const float* __restrict__ W6, const float* __restrict__ W7,
                 const float* __restrict__ x,
                 __half* __restrict__ T, __half* __restrict__ act)
{
    const int z = blockIdx.z;
    if (z == 8) {
        const int b = blockIdx.y * 64 + blockIdx.x;       // 0..1023
        const int m = b * 8 + (threadIdx.x >> 5);         // 8 rows per block
        const int jBase = (threadIdx.x & 31) * 8;
        #pragma unroll
        for (int it = 0; it < 4; ++it) {
            const int j = jBase + it * 256;
            float4 v0 = *reinterpret_cast<const float4*>(&x[(size_t)m * XCOLS + DHALF + j]);
            float4 v1 = *reinterpret_cast<const float4*>(&x[(size_t)m * XCOLS + DHALF + j + 4]);
            uint4 o;
            o.x = pack_h2(__float2half(v0.x), __float2half(v0.y));
            o.y = pack_h2(__float2half(v0.z), __float2half(v0.w));
            o.z = pack_h2(__float2half(v1.x), __float2half(v1.y));
            o.w = pack_h2(__float2half(v1.z), __float2half(v1.w));
            *reinterpret_cast<uint4*>(&act[(size_t)m * DHALF + j]) = o;
        }
        return;
    }

    const float* Ws[8] = {W0, W1, W2, W3, W4, W5, W6, W7};
    const float* W = Ws[z];
    const int typeW2 = (z >> 1) & 1;
    const int K = typeW2 ? HID : DHALF;
    const int N = typeW2 ? DHALF : HID;
    const int n0 = typeW2 ? blockIdx.y * 64 : blockIdx.x * 64;
    const int k0 = typeW2 ? blockIdx.x * 64 : blockIdx.y * 64;
    __half* t_out = T + (size_t)z * WSLOT;

    __shared__ float t[64][65];
    const int tid = threadIdx.x;
    const int lrow = tid >> 4;
    const int lc4  = (tid & 15) * 4;
    #pragma unroll
    for (int i = 0; i < 4; ++i) {
        const int rr = lrow + i * 16;
        float4 v = *reinterpret_cast<const float4*>(&W[(size_t)(k0 + rr) * N + n0 + lc4]);
        t[rr][lc4 + 0] = v.x;
        t[rr][lc4 + 1] = v.y;
        t[rr][lc4 + 2] = v.z;
        t[rr][lc4 + 3] = v.w;
    }
    __syncthreads();

    const int n  = tid >> 2;
    const int kc = (tid & 3) * 16;
    uint4 v0, v1;
    v0.x = pack_h2(__float2half(t[kc +  0][n]), __float2half(t[kc +  1][n]));
    v0.y = pack_h2(__float2half(t[kc +  2][n]), __float2half(t[kc +  3][n]));
    v0.z = pack_h2(__float2half(t[kc +  4][n]), __float2half(t[kc +  5][n]));
    v0.w = pack_h2(__float2half(t[kc +  6][n]), __float2half(t[kc +  7][n]));
    v1.x = pack_h2(__float2half(t[kc +  8][n]), __float2half(t[kc +  9][n]));
    v1.y = pack_h2(__float2half(t[kc + 10][n]), __float2half(t[kc + 11][n]));
    v1.z = pack_h2(__float2half(t[kc + 12][n]), __float2half(t[kc + 13][n]));
    v1.w = pack_h2(__float2half(t[kc + 14][n]), __float2half(t[kc + 15][n]));
    __half* dst = &t_out[(size_t)(n0 + n) * K + k0 + kc];
    *reinterpret_cast<uint4*>(dst)     = v0;
    *reinterpret_cast<uint4*>(dst + 8) = v1;
}

// ---------------------------------------------------------------------------
// Coupling epilogue
// ---------------------------------------------------------------------------
__global__ __launch_bounds__(256)
void ew_couple(const float* __restrict__ x,
               const float* __restrict__ spre,
               const float* __restrict__ tval,
               float* __restrict__ y,
               float* __restrict__ logdet,
               __half* __restrict__ act,
               int xColOff, int yColOff, int addLogdet, int writeAct)
{
    const int m = blockIdx.x;
    const int j = threadIdx.x * 4;

    float4 sp = *reinterpret_cast<const float4*>(&spre[(size_t)m * DHALF + j]);
    float4 tv = *reinterpret_cast<const float4*>(&tval[(size_t)m * DHALF + j]);
    float4 xv = *reinterpret_cast<const float4*>(&x[(size_t)m * XCOLS + xColOff + j]);

    float s0 = tanhf(sp.x), s1 = tanhf(sp.y), s2 = tanhf(sp.z), s3 = tanhf(sp.w);

    float4 o;
    o.x = xv.x * expf(s0) + tv.x;
    o.y = xv.y * expf(s1) + tv.y;
    o.z = xv.z * expf(s2) + tv.z;
    o.w = xv.w * expf(s3) + tv.w;
    *reinterpret_cast<float4*>(&y[(size_t)m * XCOLS + yColOff + j]) = o;

    if (writeAct) {
        uint2 av = make_uint2(pack_h2(__float2half(o.x), __float2half(o.y)),
                              pack_h2(__float2half(o.z), __float2half(o.w)));
        *reinterpret_cast<uint2*>(&act[(size_t)m * DHALF + j]) = av;
    }

    float lsum = s0 + s1 + s2 + s3;
    #pragma unroll
    for (int off = 16; off > 0; off >>= 1)
        lsum += __shfl_xor_sync(0xFFFFFFFFu, lsum, off);

    __shared__ float wsum[8];
    if ((threadIdx.x & 31) == 0) wsum[threadIdx.x >> 5] = lsum;
    __syncthreads();
    if (threadIdx.x == 0) {
        float tot = 0.0f;
        #pragma unroll
        for (int w = 0; w < 8; ++w) tot += wsum[w];
        if (addLogdet) logdet[m] += tot;
        else           logdet[m]  = tot;
    }
}

// ---------------------------------------------------------------------------
extern "C" void kernel_launch(void* const* d_in, const int* in_sizes, int n_in,
                              void* d_out, int out_size)
{
    (void)in_sizes; (void)n_in; (void)out_size;

    const float* x = (const float*)d_in[0];
    const float* Wslot[8] = { (const float*)d_in[1],  (const float*)d_in[5],
                              (const float*)d_in[3],  (const float*)d_in[7],
                              (const float*)d_in[9],  (const float*)d_in[13],
                              (const float*)d_in[11], (const float*)d_in[15] };
    const float* s1_b1 = (const float*)d_in[2];
    const float* s1_b2 = (const float*)d_in[4];
    const float* t1_b1 = (const float*)d_in[6];
    const float* t1_b2 = (const float*)d_in[8];
    const float* s2_b1 = (const float*)d_in[10];
    const float* s2_b2 = (const float*)d_in[12];
    const float* t2_b1 = (const float*)d_in[14];
    const float* t2_b2 = (const float*)d_in[16];

    float* y      = (float*)d_out;
    float* logdet = y + (size_t)BATCH * XCOLS;

    __half *act, *hid, *wt;
    float *sbuf, *tbuf;
    cudaGetSymbolAddress((void**)&act, g_act);
    cudaGetSymbolAddress((void**)&hid, g_hid);
    cudaGetSymbolAddress((void**)&wt,  g_wt);
    cudaGetSymbolAddress((void**)&sbuf, g_s);
    cudaGetSymbolAddress((void**)&tbuf, g_t);

    cudaFuncSetAttribute(gemm_l1, cudaFuncAttributeMaxDynamicSharedMemorySize, L1_SMEM);
    cudaFuncSetAttribute(gemm_l2, cudaFuncAttributeMaxDynamicSharedMemorySize, L2_SMEM);

    convert_all<<<dim3(64, 16, 9), 256>>>(Wslot[0], Wslot[1], Wslot[2], Wslot[3],
                                          Wslot[4], Wslot[5], Wslot[6], Wslot[7],
                                          x, wt, act);

    dim3 gridL1(L1_N / 128, BATCH / 128);        // 64 x 64
    dim3 gridL2(DHALF / 128, BATCH / 64, 2);     // 8 x 128 x 2

    // phase 1
    gemm_l1<<<gridL1, 256, L1_SMEM>>>(act, wt + 0 * WSLOT, s1_b1, t1_b1, hid);
    gemm_l2<<<gridL2, 256, L2_SMEM>>>(hid, wt + 2 * WSLOT, s1_b2, t1_b2, sbuf, tbuf);
    ew_couple<<<BATCH, 256>>>(x, sbuf, tbuf, y, logdet, act, 0, 0, 0, 1);

    // phase 2
    gemm_l1<<<gridL1, 256, L1_SMEM>>>(act, wt + 4 * WSLOT, s2_b1, t2_b1, hid);
    gemm_l2<<<gridL2, 256, L2_SMEM>>>(hid, wt + 6 * WSLOT, s2_b2, t2_b2, sbuf, tbuf);
    ew_couple<<<BATCH, 256>>>(x, sbuf, tbuf, y, logdet, nullptr, DHALF, DHALF, 1, 0);
}